// round 8
// baseline (speedup 1.0000x reference)
#include <cuda_runtime.h>
#include <cuda_bf16.h>

// ---------------- problem constants ----------------
#define EDG   16384
#define NNODE 512
#define NB    8
#define NT    16
#define HD    64            // C == H == 64
#define NSLAB (NB*NT)       // 128
#define NROW  (NB*NNODE)    // 4096 rows of state per step
#define NPC   384           // P columns: 2 layers * (z64|r64|t64)

// ---------------- device scratch (static; no allocation) ----------------
__device__ __align__(16) float g_deg[NNODE];
__device__ __align__(16) float g_dinv[NNODE];
__device__ int   g_cnt[NNODE];
__device__ int   g_rowptr[NNODE + 1];
__device__ int   g_cursor[NNODE];
__device__ __align__(16) int   g_col[EDG];
__device__ __align__(16) float g_val[EDG];
__device__ int   g_w64;     // 1 if edge_index buffer is int64, 0 if int32

__device__ __align__(16) float g_X1[NSLAB * NNODE * HD];   // Lx(x)
__device__ __align__(16) float g_X2[NSLAB * NNODE * HD];   // 2Lx(X1)-x

__device__ __align__(16) float g_P[(long)NSLAB * NNODE * NPC];  // x-side preacts + bias (100.7 MB)

__device__ __align__(16) float g_h [NROW * HD];            // GRU state
__device__ __align__(16) float g_z [NROW * HD];
__device__ __align__(16) float g_hr[NROW * HD];
__device__ __align__(16) float g_U1[NROW * HD];
__device__ __align__(16) float g_U2[NROW * HD];

__device__ __align__(16) float g_Wxall[192 * NPC];         // [kk=s*64+c][col=l*192+g*64+h]
__device__ __align__(16) float g_ball[NPC];                // bx+bh per col
__device__ __align__(16) float g_Whzr[2][192 * 128];       // h-side z,r weights
__device__ __align__(16) float g_Whht[2][192 * 64];        // h-side h-tilde weights

__device__ __align__(16) float g_sp[NROW * HD];
__device__ __align__(16) float g_tp[NROW * HD];            // includes +b1

// ---------------- setup kernels ----------------
__global__ void k_init() {
    int i = blockIdx.x * blockDim.x + threadIdx.x;
    int nstate = NROW * HD;
    for (int j = i; j < nstate; j += gridDim.x * blockDim.x) g_h[j] = 0.f;
    if (i < NNODE) { g_deg[i] = 0.f; g_cnt[i] = 0; }
}

// Detect edge_index element width (int64 -> odd 32-bit words all zero).
__global__ void k_detect(const int* __restrict__ ei32) {
    if (threadIdx.x == 0) {
        int any = 0;
        for (int i = 0; i < 128; ++i) any |= ei32[2 * i + 1];
        g_w64 = (any == 0) ? 1 : 0;
    }
}

__device__ __forceinline__ void load_edge(const void* ei, int e, int& s, int& d) {
    if (g_w64) {
        const long long* p = (const long long*)ei;
        s = (int)p[e]; d = (int)p[EDG + e];
    } else {
        const int* p = (const int*)ei;
        s = p[e]; d = p[EDG + e];
    }
}

__global__ void k_deg(const void* __restrict__ ei, const float* __restrict__ ew) {
    int e = blockIdx.x * blockDim.x + threadIdx.x;
    if (e >= EDG) return;
    int s, d;
    load_edge(ei, e, s, d);
    if ((unsigned)s >= NNODE || (unsigned)d >= NNODE) return;
    atomicAdd(&g_deg[s], ew[e]);
    atomicAdd(&g_cnt[d], 1);
}

__global__ void k_scan() {   // 1 block, 512 threads
    int i = threadIdx.x;
    float dg = g_deg[i];
    g_dinv[i] = (dg > 0.f) ? rsqrtf(fmaxf(dg, 1e-12f)) : 0.f;
    __shared__ int sc[NNODE];
    sc[i] = g_cnt[i];
    __syncthreads();
    for (int off = 1; off < NNODE; off <<= 1) {
        int v = (i >= off) ? sc[i - off] : 0;
        __syncthreads();
        sc[i] += v;
        __syncthreads();
    }
    if (i == 0) g_rowptr[0] = 0;
    g_rowptr[i + 1] = sc[i];
    g_cursor[i] = (i == 0) ? 0 : sc[i - 1];
}

__global__ void k_fill(const void* __restrict__ ei, const float* __restrict__ ew) {
    int e = blockIdx.x * blockDim.x + threadIdx.x;
    if (e >= EDG) return;
    int s, d;
    load_edge(ei, e, s, d);
    if ((unsigned)s >= NNODE || (unsigned)d >= NNODE) return;
    int p = atomicAdd(&g_cursor[d], 1);
    g_col[p] = s;
    g_val[p] = -ew[e] * g_dinv[s] * g_dinv[d];
}

// pack weights. Wx[l,g,s,c,h], Wh[l,g,s,c,h]; kk = s*64+c
__global__ void k_wprep(const float* __restrict__ Wx, const float* __restrict__ bx,
                        const float* __restrict__ Wh, const float* __restrict__ bh) {
    int i = blockIdx.x * blockDim.x + threadIdx.x;
    if (i < 73728) {                       // Wxall: 192*384
        int kk = i / NPC, col = i % NPC;
        int s = kk >> 6, c = kk & 63;
        int l = col / 192, r = col % 192, g = r >> 6, h = r & 63;
        g_Wxall[i] = Wx[((((l*3+g)*3 + s)*64) + c)*64 + h];
    } else if (i < 73728 + 384) {          // ball
        int col = i - 73728;
        int l = col / 192, r = col % 192, g = r >> 6, h = r & 63;
        g_ball[col] = bx[(l*3+g)*64 + h] + bh[(l*3+g)*64 + h];
    } else if (i < 74112 + 49152) {        // Whzr: 2*192*128
        int j = i - 74112;
        int l = j / 24576, rem = j % 24576;
        int kk = rem / 128, col = rem % 128;
        int s = kk >> 6, c = kk & 63, g = col >> 6, h = col & 63;
        g_Whzr[l][rem] = Wh[((((l*3+g)*3 + s)*64) + c)*64 + h];
    } else if (i < 123264 + 24576) {       // Whht: 2*192*64
        int j = i - 123264;
        int l = j / 12288, rem = j % 12288;
        int kk = rem / 64, h = rem % 64;
        int s = kk >> 6, c = kk & 63;
        g_Whht[l][rem] = Wh[((((l*3+2)*3 + s)*64) + c)*64 + h];
    }
}

// ---------------- fused Chebyshev pair: o1 = Lx(u), o2 = 2 Lx(o1) - u ----------------
// block = (8-channel chunk, slab). smem-staged slab chunk; 256 thr = 32 node-thr x 8 ch.
__global__ void __launch_bounds__(256) k_cheb(const float* __restrict__ u,
                                              float* __restrict__ o1,
                                              float* __restrict__ o2) {
    __shared__ float su[NNODE][9];
    __shared__ float st[NNODE][9];
    int slab = blockIdx.y;
    int c0 = blockIdx.x * 8;
    int tid = threadIdx.x;
    long base = (long)slab * NNODE * HD;
    for (int q = tid; q < NNODE * 8; q += 256) {
        int n = q >> 3, c = q & 7;
        su[n][c] = u[base + (long)n * HD + c0 + c];
    }
    __syncthreads();
    int c = tid & 7, nt = tid >> 3;
    for (int n = nt; n < NNODE; n += 32) {
        int rs = g_rowptr[n], re = g_rowptr[n + 1];
        float a = 0.f;
        for (int e = rs; e < re; ++e) a += g_val[e] * su[g_col[e]][c];
        st[n][c] = a;
    }
    __syncthreads();
    for (int n = nt; n < NNODE; n += 32) {
        int rs = g_rowptr[n], re = g_rowptr[n + 1];
        float a = 0.f;
        for (int e = rs; e < re; ++e) a += g_val[e] * st[g_col[e]][c];
        long ob = base + (long)n * HD + c0 + c;
        o1[ob] = st[n][c];
        o2[ob] = 2.f * a - su[n][c];
    }
}

// ---------------- big x-side GEMM: P = [x|X1|X2] @ Wxall + ball ----------------
// M=65536 (slab-major rows), N=384, K=192. 128x128 tiles, 256 thr, TM=TN=8.
__global__ void __launch_bounds__(256) k_bigp(const float* __restrict__ x) {
    __shared__ float As[16][128];
    __shared__ float Bs[16][128];
    int tid = threadIdx.x, tx = tid & 15, ty = tid >> 4;
    int row0 = blockIdx.x * 128, n0 = blockIdx.y * 128;
    float acc[8][8];
#pragma unroll
    for (int i = 0; i < 8; ++i)
#pragma unroll
        for (int j = 0; j < 8; ++j) acc[i][j] = 0.f;

    for (int kt = 0; kt < 12; ++kt) {
        int s = kt >> 2, koff = (kt & 3) * 16;
        const float* src = (s == 0) ? x : (s == 1) ? g_X1 : g_X2;
        for (int q = tid; q < 512; q += 256) {
            int m = q >> 2, kq = q & 3;
            float4 v = *reinterpret_cast<const float4*>(src + (long)(row0 + m) * HD + koff + kq * 4);
            As[kq*4 + 0][m] = v.x; As[kq*4 + 1][m] = v.y;
            As[kq*4 + 2][m] = v.z; As[kq*4 + 3][m] = v.w;
        }
        for (int q = tid; q < 512; q += 256) {
            int kk = q >> 5, nq = q & 31;
            *reinterpret_cast<float4*>(&Bs[kk][nq * 4]) =
                *reinterpret_cast<const float4*>(g_Wxall + (long)(kt*16 + kk) * NPC + n0 + nq * 4);
        }
        __syncthreads();
#pragma unroll
        for (int k = 0; k < 16; ++k) {
            float a[8], b[8];
#pragma unroll
            for (int i = 0; i < 8; ++i) a[i] = As[k][ty * 8 + i];
#pragma unroll
            for (int j = 0; j < 8; ++j) b[j] = Bs[k][tx * 8 + j];
#pragma unroll
            for (int i = 0; i < 8; ++i)
#pragma unroll
                for (int j = 0; j < 8; ++j) acc[i][j] += a[i] * b[j];
        }
        __syncthreads();
    }
#pragma unroll
    for (int i = 0; i < 8; ++i) {
        long row = row0 + ty * 8 + i;
#pragma unroll
        for (int j = 0; j < 8; ++j) {
            int col = n0 + tx * 8 + j;
            g_P[row * NPC + col] = acc[i][j] + g_ball[col];
        }
    }
}

// ---------------- step GEMM (h-side only, K=192) + P add + GRU epilogue ----------------
// MODE 1: N=128 (z|r): z = sigmoid, hr = r*h.  MODE 2: N=64: h = z*h + (1-z)*tanh.
template<int BM, int BN, int MODE>
__global__ void __launch_bounds__(256) k_gemm(
    const float* __restrict__ d0, const float* __restrict__ d1, const float* __restrict__ d2,
    const float* __restrict__ W, const float* __restrict__ Pg, int t) {
    constexpr int NW = (MODE == 1) ? 128 : 64;
    constexpr int TM = BM / 16, TN = BN / 16;
    __shared__ float As[16][BM];
    __shared__ float Bs[16][BN];
    int tid = threadIdx.x;
    int tx = tid & 15, ty = tid >> 4;
    int row0 = blockIdx.x * BM;
    int n0 = blockIdx.y * BN;
    float acc[TM][TN];
#pragma unroll
    for (int i = 0; i < TM; ++i)
#pragma unroll
        for (int j = 0; j < TN; ++j) acc[i][j] = 0.f;

    for (int kt = 0; kt < 12; ++kt) {
        int s = kt >> 2, koff = (kt & 3) * 16;
        const float* src = (s == 0) ? d0 : (s == 1) ? d1 : d2;
        for (int q = tid; q < BM * 4; q += 256) {
            int m = q >> 2, kq = q & 3;
            float4 v = *reinterpret_cast<const float4*>(src + (long)(row0 + m) * HD + koff + kq * 4);
            As[kq*4 + 0][m] = v.x; As[kq*4 + 1][m] = v.y;
            As[kq*4 + 2][m] = v.z; As[kq*4 + 3][m] = v.w;
        }
        constexpr int QPK = BN / 4;
        for (int q = tid; q < BN * 4; q += 256) {
            int kk = q / QPK, nq = q % QPK;
            *reinterpret_cast<float4*>(&Bs[kk][nq * 4]) =
                *reinterpret_cast<const float4*>(W + (long)(kt*16 + kk) * NW + n0 + nq * 4);
        }
        __syncthreads();
#pragma unroll
        for (int k = 0; k < 16; ++k) {
            float a[TM], b[TN];
#pragma unroll
            for (int i = 0; i < TM; ++i) a[i] = As[k][ty * TM + i];
#pragma unroll
            for (int j = 0; j < TN; ++j) b[j] = Bs[k][tx * TN + j];
#pragma unroll
            for (int i = 0; i < TM; ++i)
#pragma unroll
                for (int j = 0; j < TN; ++j) acc[i][j] += a[i] * b[j];
        }
        __syncthreads();
    }

#pragma unroll
    for (int i = 0; i < TM; ++i) {
        int row = row0 + ty * TM + i;
        long prow = (long)((((row >> 9) * NT + t) << 9) | (row & 511));
#pragma unroll
        for (int j = 0; j < TN; ++j) {
            int col = n0 + tx * TN + j;
            float pre = acc[i][j] + Pg[prow * NPC + col];
            if (MODE == 1) {
                float sg = 1.f / (1.f + __expf(-pre));
                int hc = col & 63;
                if (col < 64) g_z[row * HD + hc] = sg;
                else          g_hr[row * HD + hc] = sg * g_h[row * HD + hc];
            } else {
                float th = tanhf(pre);
                float z  = g_z[row * HD + col];
                float ho = g_h[row * HD + col];
                g_h[row * HD + col] = z * ho + (1.f - z) * th;
            }
        }
    }
}

// ---------------- link predictor ----------------
__global__ void k_proj(const float* __restrict__ W1, const float* __restrict__ b1) {
    int r = blockIdx.x;
    int j = threadIdx.x;
    __shared__ float hrow[HD];
    if (j < HD) hrow[j] = g_h[(long)r * HD + j];
    __syncthreads();
    int hc = j & 63;
    bool isT = (j >= 64);
    int off = isT ? 64 : 0;
    float acc = 0.f;
#pragma unroll 8
    for (int c = 0; c < HD; ++c) acc += hrow[c] * W1[(off + c) * 64 + hc];
    if (isT) g_tp[(long)r * HD + hc] = acc + b1[hc];
    else     g_sp[(long)r * HD + hc] = acc;
}

__global__ void __launch_bounds__(256) k_pair(const float* __restrict__ W2,
                                              const float* __restrict__ b2,
                                              float* __restrict__ out) {
    __shared__ float ssp[32][65];
    __shared__ float stp[32][65];
    __shared__ float sw2[64];
    int b  = blockIdx.z;
    int s0 = blockIdx.y * 32;
    int t0 = blockIdx.x * 32;
    int tid = threadIdx.x;
    for (int q = tid; q < 32 * 64; q += 256) {
        int row = q >> 6, c = q & 63;
        ssp[row][c] = g_sp[((long)(b * NNODE + s0 + row)) * HD + c];
        stp[row][c] = g_tp[((long)(b * NNODE + t0 + row)) * HD + c];
    }
    if (tid < 64) sw2[tid] = W2[tid];
    __syncthreads();
    int si = tid >> 3;
    int tb = (tid & 7) * 4;
    float a0 = 0.f, a1 = 0.f, a2 = 0.f, a3 = 0.f;
#pragma unroll 4
    for (int h = 0; h < HD; ++h) {
        float a = ssp[si][h];
        float w = sw2[h];
        a0 += fmaxf(a + stp[tb + 0][h], 0.f) * w;
        a1 += fmaxf(a + stp[tb + 1][h], 0.f) * w;
        a2 += fmaxf(a + stp[tb + 2][h], 0.f) * w;
        a3 += fmaxf(a + stp[tb + 3][h], 0.f) * w;
    }
    float bb = b2[0];
    long ob = ((long)(b * NNODE + s0 + si)) * NNODE + t0 + tb;
    out[ob + 0] = a0 + bb;
    out[ob + 1] = a1 + bb;
    out[ob + 2] = a2 + bb;
    out[ob + 3] = a3 + bb;
}

// ---------------- launch ----------------
extern "C" void kernel_launch(void* const* d_in, const int* in_sizes, int n_in,
                              void* d_out, int out_size) {
    const float* x  = (const float*)d_in[0];
    const float* ew = (const float*)d_in[1];
    const float* Wx = (const float*)d_in[2];
    const float* bx = (const float*)d_in[3];
    const float* Wh = (const float*)d_in[4];
    const float* bh = (const float*)d_in[5];
    const float* W1 = (const float*)d_in[6];
    const float* b1 = (const float*)d_in[7];
    const float* W2 = (const float*)d_in[8];
    const float* b2 = (const float*)d_in[9];
    const void*  ei = d_in[10];
    float* out = (float*)d_out;

    float *pX1, *pX2, *ph, *phr, *pU1, *pU2, *pP, *pWhzr, *pWhht;
    cudaGetSymbolAddress((void**)&pX1,   g_X1);
    cudaGetSymbolAddress((void**)&pX2,   g_X2);
    cudaGetSymbolAddress((void**)&ph,    g_h);
    cudaGetSymbolAddress((void**)&phr,   g_hr);
    cudaGetSymbolAddress((void**)&pU1,   g_U1);
    cudaGetSymbolAddress((void**)&pU2,   g_U2);
    cudaGetSymbolAddress((void**)&pP,    g_P);
    cudaGetSymbolAddress((void**)&pWhzr, g_Whzr);
    cudaGetSymbolAddress((void**)&pWhht, g_Whht);

    // graph structure + weight packing
    k_init<<<256, 1024>>>();
    k_detect<<<1, 32>>>((const int*)ei);
    k_deg<<<(EDG + 255) / 256, 256>>>(ei, ew);
    k_scan<<<1, NNODE>>>();
    k_fill<<<(EDG + 255) / 256, 256>>>(ei, ew);
    k_wprep<<<(147840 + 255) / 256, 256>>>(Wx, bx, Wh, bh);

    // x Chebyshev basis for all (b,t) slabs: one fused launch
    k_cheb<<<dim3(8, NSLAB), 256>>>(x, pX1, pX2);

    // hoisted x-side projections for all t, l, gates
    k_bigp<<<dim3(512, 3), 256>>>(x);

    // recurrent steps
    for (int t = 0; t < NT; ++t) {
        for (int l = 0; l < 2; ++l) {
            k_cheb<<<dim3(8, NB), 256>>>(ph, pU1, pU2);
            k_gemm<64, 64, 1><<<dim3(NROW / 64, 2), 256>>>(
                ph, pU1, pU2, pWhzr + (long)l * 192 * 128, pP + (long)l * 192, t);
            k_cheb<<<dim3(8, NB), 256>>>(phr, pU1, pU2);
            k_gemm<32, 64, 2><<<dim3(NROW / 32, 1), 256>>>(
                phr, pU1, pU2, pWhht + (long)l * 192 * 64, pP + (long)l * 192 + 128, t);
        }
    }

    // predictor
    k_proj<<<NROW, 128>>>(W1, b1);
    k_pair<<<dim3(NNODE / 32, NNODE / 32, NB), 256>>>(W2, b2, out);
}